// round 16
// baseline (speedup 1.0000x reference)
#include <cuda_runtime.h>
#include <cuda_bf16.h>
#include <cstdint>

#define NPTS   64
#define NANGS  2016
#define NCOLS  300000
#define LSEG   (NANGS / 2)     // 1008
#define SROWS  66              // 64 state rows + 2 pad (preload overrun)
#define NBLOCKS ((NCOLS + 127) / 128)   // 2344

typedef unsigned int u32;

__device__ float g_R[NPTS * NPTS];
__device__ int   g_ready = 0;
__device__ int   g_done  = 0;

__device__ __forceinline__ u32 smem_u32(const void* p) {
    u32 a;
    asm("{ .reg .u64 t; cvta.to.shared.u64 t, %1; cvt.u32.u64 %0, t; }"
        : "=r"(a) : "l"(p));
    return a;
}

// Shared-memory overlay (dynamic, 50 KB):
//  build (block 0, prologue): cs[2024] float2 | S0[66*64] | S1[66*64]
//  gemm  (all blocks, after): RhiS[64*36] u32 | RloS[64*36] u32
#define CS_ELEMS   (NANGS + 8)
#define S0_OFF     (CS_ELEMS * 8)                 // bytes
#define S1_OFF     (S0_OFF + SROWS * NPTS * 4)
#define SMEM_BYTES (S1_OFF + SROWS * NPTS * 4)    // 49984

#define LDR 36

#define CVT_PACK(d, x1, x0) \
    asm("cvt.rn.bf16x2.f32 %0, %1, %2;" : "=r"(d) : "f"(x1), "f"(x0))

#define LDMX4(R0, R1, R2, R3, ADDR)                                            \
    asm volatile("ldmatrix.sync.aligned.m8n8.x4.shared.b16 {%0,%1,%2,%3}, [%4];" \
                 : "=r"(R0), "=r"(R1), "=r"(R2), "=r"(R3) : "r"(ADDR))

#define MMA_BF16(ACC, A0, A1, A2, A3, B0, B1)                                  \
    asm volatile(                                                              \
        "mma.sync.aligned.m16n8k16.row.col.f32.bf16.bf16.f32 "                 \
        "{%0,%1,%2,%3},{%4,%5,%6,%7},{%8,%9},{%0,%1,%2,%3};"                   \
        : "+f"(ACC[0]), "+f"(ACC[1]), "+f"(ACC[2]), "+f"(ACC[3])               \
        : "r"(A0), "r"(A1), "r"(A2), "r"(A3), "r"(B0), "r"(B1))

extern __shared__ char smx[];

// ---------------------------------------------------------------------------
// Block-0 prologue: build R = diag(mus) * M1 @ M0 in shared memory.
// Phase 1 (threads 0-127): two 1008-rotation chains, 2-wide software-pipelined
// (rb/(c,s) for rotations b+2,b+3 loaded BEFORE the stores of rotation b).
// Phase 2 (all 256 threads): 64x64x64 combine + mus, written to g_R.
// ---------------------------------------------------------------------------
__device__ void build_R_block0(const float* __restrict__ angles,
                               const float* __restrict__ mus) {
    float2* cs = reinterpret_cast<float2*>(smx);
    float*  S0 = reinterpret_cast<float*>(smx + S0_OFF);
    float*  S1 = reinterpret_cast<float*>(smx + S1_OFF);
    const int tid = threadIdx.x;

    for (int i = tid; i < CS_ELEMS; i += 256) {
        if (i < NANGS) {
            float sv, cv;
            __sincosf(angles[i], &sv, &cv);
            cs[i] = make_float2(cv, sv);
        } else {
            cs[i] = make_float2(1.0f, 0.0f);
        }
    }
    for (int idx = tid; idx < SROWS * NPTS; idx += 256) {
        const int r = idx >> 6, c = idx & 63;
        const float v = (r == c) ? 1.0f : 0.0f;
        S0[idx] = v;
        S1[idx] = v;
    }
    __syncthreads();

    if (tid < 2 * NPTS) {
        const int s  = tid >> 6;
        const int j  = tid & 63;
        float* Sl    = (s == 0) ? S0 : S1;
        const int i0 = s * LSEG;
        const int i1 = i0 + LSEG;

#pragma unroll 1
        for (int t = 0; t < NPTS - 1; t++) {
            const int gs   = t * (2 * NPTS - 1 - t) / 2;
            const int glen = NPTS - 1 - t;
            if (gs >= i1) break;
            if (gs + glen <= i0) continue;
            int lo = i0 - gs; if (lo < 0) lo = 0;
            int hi = i1 - gs; if (hi > glen) hi = glen;
            const int bstart = t + 1 + lo;
            const int bend   = t + 1 + hi;
            const int cbase  = gs - (t + 1);

            float rt = Sl[t * NPTS + j];

            float  rbA = Sl[bstart * NPTS + j];
            float  rbB = Sl[(bstart + 1) * NPTS + j];
            float2 pA  = cs[cbase + bstart];
            float2 pB  = cs[cbase + bstart + 1];

            int bb = bstart;
#pragma unroll 1
            for (; bb + 2 <= bend; bb += 2) {
                const float  rb2 = Sl[(bb + 2) * NPTS + j];
                const float  rb3 = Sl[(bb + 3) * NPTS + j];
                const float2 p2  = cs[cbase + bb + 2];
                const float2 p3  = cs[cbase + bb + 3];

                Sl[bb * NPTS + j] = fmaf(pA.y, rt, pA.x * rbA);
                rt = fmaf(pA.x, rt, -(pA.y * rbA));
                Sl[(bb + 1) * NPTS + j] = fmaf(pB.y, rt, pB.x * rbB);
                rt = fmaf(pB.x, rt, -(pB.y * rbB));

                rbA = rb2; rbB = rb3; pA = p2; pB = p3;
            }
            if (bb < bend) {
                Sl[bb * NPTS + j] = fmaf(pA.y, rt, pA.x * rbA);
                rt = fmaf(pA.x, rt, -(pA.y * rbA));
            }
            Sl[t * NPTS + j] = rt;
        }
    }
    __syncthreads();

    // Phase 2: g_R = diag(mus) * (S1 @ S0); thread -> (row, 16-col group)
    {
        const int r  = tid >> 2;           // 0..63
        const int cg = (tid & 3) * 16;     // 0,16,32,48

        float acc[16];
#pragma unroll
        for (int i = 0; i < 16; i++) acc[i] = 0.0f;

#pragma unroll 4
        for (int k = 0; k < NPTS; k++) {
            const float a = S1[r * NPTS + k];
            const float* brow = &S0[k * NPTS + cg];
#pragma unroll
            for (int q = 0; q < 4; q++) {
                const float4 b = *reinterpret_cast<const float4*>(brow + q * 4);
                acc[q * 4 + 0] = fmaf(a, b.x, acc[q * 4 + 0]);
                acc[q * 4 + 1] = fmaf(a, b.y, acc[q * 4 + 1]);
                acc[q * 4 + 2] = fmaf(a, b.z, acc[q * 4 + 2]);
                acc[q * 4 + 3] = fmaf(a, b.w, acc[q * 4 + 3]);
            }
        }

        const float m = mus[r];
#pragma unroll
        for (int q = 0; q < 4; q++) {
            float4 o = make_float4(m * acc[q * 4 + 0], m * acc[q * 4 + 1],
                                   m * acc[q * 4 + 2], m * acc[q * 4 + 3]);
            *reinterpret_cast<float4*>(&g_R[r * NPTS + cg + q * 4]) = o;
        }
    }
    __syncthreads();   // build smem dead; safe to overlay with gemm smem
}

// ---------------------------------------------------------------------------
// Fused kernel: block 0 builds R, everyone else waits on g_ready, then all
// blocks run the proven R5 gemm (bf16 split 3-term HMMA, warp tile 64x16).
// Last block to finish resets the flags (graph-replay deterministic).
// ---------------------------------------------------------------------------
__global__ void __launch_bounds__(256, 3)
fused_kernel(const float* __restrict__ X, float* __restrict__ Y,
             const float* __restrict__ angles, const float* __restrict__ mus) {
    u32* RhiS = reinterpret_cast<u32*>(smx);
    u32* RloS = RhiS + NPTS * LDR;

    if (blockIdx.x == 0) {
        build_R_block0(angles, mus);
        __threadfence();
        __syncthreads();
        if (threadIdx.x == 0) atomicExch(&g_ready, 1);
    } else {
        if (threadIdx.x == 0) {
            while (atomicAdd(&g_ready, 0) == 0) { __nanosleep(128); }
        }
        __syncthreads();
        __threadfence();
    }

    // ---- pack R -> (hi, lo) bf16x2 in smem ----
    for (int idx = threadIdx.x; idx < NPTS * 32; idx += 256) {
        const int row = idx >> 5, kp = idx & 31;
        const float x0 = g_R[row * NPTS + 2 * kp];
        const float x1 = g_R[row * NPTS + 2 * kp + 1];
        u32 hh; CVT_PACK(hh, x1, x0);
        const float h0 = __uint_as_float(hh << 16);
        const float h1 = __uint_as_float(hh & 0xFFFF0000u);
        u32 ll; CVT_PACK(ll, x1 - h1, x0 - h0);
        RhiS[row * LDR + kp] = hh;
        RloS[row * LDR + kp] = ll;
    }
    __syncthreads();

    const int warp = threadIdx.x >> 5;
    const int lane = threadIdx.x & 31;
    const int g = lane >> 2;
    const int t = lane & 3;

    const long n0 = (long)blockIdx.x * 128 + warp * 16;
    if (n0 + 16 <= NCOLS) {
        const int r8   = lane & 7;
        const int selm = (lane >> 3) & 1;
        const int selk = (lane >> 4) & 1;
        const u32 laneoff = (u32)(((selm * 8 + r8) * LDR + selk * 4) * 4);
        const u32 ahibase = smem_u32(RhiS) + laneoff;
        const u32 alobase = smem_u32(RloS) + laneoff;

        float acc[4][2][4];
#pragma unroll
        for (int mt = 0; mt < 4; mt++)
#pragma unroll
            for (int nt = 0; nt < 2; nt++)
#pragma unroll
                for (int q = 0; q < 4; q++) acc[mt][nt][q] = 0.0f;

        const float* __restrict__ xb = X + n0 + g;
        float raw[2][8];

#define LOADK(BUF, KS)                                                         \
        do {                                                                   \
            const size_t o  = (size_t)((KS)*16 + 2 * t) * NCOLS;               \
            const size_t o8 = o + (size_t)8 * NCOLS;                           \
            raw[BUF][0] = xb[o];      raw[BUF][1] = xb[o + NCOLS];             \
            raw[BUF][2] = xb[o8];     raw[BUF][3] = xb[o8 + NCOLS];            \
            raw[BUF][4] = xb[o + 8];  raw[BUF][5] = xb[o + NCOLS + 8];         \
            raw[BUF][6] = xb[o8 + 8]; raw[BUF][7] = xb[o8 + NCOLS + 8];        \
        } while (0)

        LOADK(0, 0);
        LOADK(1, 1);

#pragma unroll
        for (int ks = 0; ks < 4; ks++) {
            const int cur = ks & 1;

            u32 bhi[2][2], blo[2][2];
#pragma unroll
            for (int nt = 0; nt < 2; nt++) {
#pragma unroll
                for (int h2 = 0; h2 < 2; h2++) {
                    const float x0 = raw[cur][nt * 4 + h2 * 2];
                    const float x1 = raw[cur][nt * 4 + h2 * 2 + 1];
                    u32 hh; CVT_PACK(hh, x1, x0);
                    const float h0 = __uint_as_float(hh << 16);
                    const float h1 = __uint_as_float(hh & 0xFFFF0000u);
                    u32 ll; CVT_PACK(ll, x1 - h1, x0 - h0);
                    bhi[nt][h2] = hh;
                    blo[nt][h2] = ll;
                }
            }

            if (ks + 2 < 4) LOADK(cur, ks + 2);

#pragma unroll
            for (int mt = 0; mt < 4; mt++) {
                const u32 off = (u32)(mt * 16 * LDR * 4 + ks * 32);
                u32 ah0, ah1, ah2, ah3, al0, al1, al2, al3;
                LDMX4(ah0, ah1, ah2, ah3, ahibase + off);
                LDMX4(al0, al1, al2, al3, alobase + off);
#pragma unroll
                for (int nt = 0; nt < 2; nt++) {
                    MMA_BF16(acc[mt][nt], ah0, ah1, ah2, ah3, bhi[nt][0], bhi[nt][1]);
                    MMA_BF16(acc[mt][nt], ah0, ah1, ah2, ah3, blo[nt][0], blo[nt][1]);
                    MMA_BF16(acc[mt][nt], al0, al1, al2, al3, bhi[nt][0], bhi[nt][1]);
                }
            }
        }
#undef LOADK

#pragma unroll
        for (int mt = 0; mt < 4; mt++) {
            const int r0 = mt * 16 + g;
#pragma unroll
            for (int nt = 0; nt < 2; nt++) {
                const long col = n0 + 8 * nt + 2 * t;
                *reinterpret_cast<float2*>(Y + (size_t)r0 * NCOLS + col) =
                    make_float2(acc[mt][nt][0], acc[mt][nt][1]);
                *reinterpret_cast<float2*>(Y + (size_t)(r0 + 8) * NCOLS + col) =
                    make_float2(acc[mt][nt][2], acc[mt][nt][3]);
            }
        }
    }

    // ---- flag reset by the last-finishing block (replay-deterministic) ----
    __syncthreads();
    if (threadIdx.x == 0) {
        if (atomicAdd(&g_done, 1) == NBLOCKS - 1) {
            g_ready = 0;
            g_done  = 0;
            __threadfence();
        }
    }
}

// ---------------------------------------------------------------------------
// Inputs (metadata order): X (64*300000 f32), angles (2016 f32), mus (64 f32).
// ---------------------------------------------------------------------------
extern "C" void kernel_launch(void* const* d_in, const int* in_sizes, int n_in,
                              void* d_out, int out_size) {
    const float* X      = (const float*)d_in[0];
    const float* angles = (const float*)d_in[1];
    const float* mus    = (const float*)d_in[2];
    float* Y            = (float*)d_out;

    static int configured = 0;
    if (!configured) {
        cudaFuncSetAttribute(fused_kernel,
                             cudaFuncAttributeMaxDynamicSharedMemorySize, SMEM_BYTES);
        configured = 1;
    }

    fused_kernel<<<NBLOCKS, 256, SMEM_BYTES>>>(X, Y, angles, mus);
}

// round 17
// speedup vs baseline: 1.1145x; 1.1145x over previous
#include <cuda_runtime.h>
#include <cuda_bf16.h>
#include <cstdint>

#define NPTS   64
#define NANGS  2016
#define NCOLS  300000
#define NSEG   8
#define LSEG   (NANGS / NSEG)   // 252

typedef unsigned int u32;

__device__ float g_M[NSEG * NPTS * NPTS];
__device__ float g_P[(NSEG/2) * NPTS * NPTS];
__device__ float g_Q[(NSEG/4) * NPTS * NPTS];
__device__ float g_R[NPTS * NPTS];

__device__ __forceinline__ u32 smem_u32(const void* p) {
    u32 a;
    asm("{ .reg .u64 t; cvta.to.shared.u64 t, %1; cvt.u32.u64 %0, t; }"
        : "=r"(a) : "l"(p));
    return a;
}

// ---------------------------------------------------------------------------
// Build (R5-proven): 8 segment matrices + 3-level product tree.
// ---------------------------------------------------------------------------
__global__ void __launch_bounds__(NPTS, 1)
build_seg_kernel(const float* __restrict__ angles) {
    __shared__ float2 cs[LSEG];
    __shared__ float  Rs[NPTS * NPTS];

    const int j  = threadIdx.x;
    const int i0 = blockIdx.x * LSEG;
    const int i1 = i0 + LSEG;

    for (int i = j; i < LSEG; i += NPTS) {
        float sv, cv;
        __sincosf(angles[i0 + i], &sv, &cv);
        cs[i] = make_float2(cv, sv);
    }
    for (int r = 0; r < NPTS; r++) Rs[r * NPTS + j] = (r == j) ? 1.0f : 0.0f;
    __syncthreads();

#pragma unroll 1
    for (int t = 0; t < NPTS - 1; t++) {
        const int gs   = t * (2 * NPTS - 1 - t) / 2;
        const int glen = NPTS - 1 - t;
        if (gs >= i1) break;
        if (gs + glen <= i0) continue;
        int lo = i0 - gs; if (lo < 0) lo = 0;
        int hi = i1 - gs; if (hi > glen) hi = glen;

        float rt = Rs[t * NPTS + j];
#pragma unroll 7
        for (int b = t + 1 + lo; b < t + 1 + hi; b++) {
            const float2 p  = cs[gs + (b - t - 1) - i0];
            const float  rb = Rs[b * NPTS + j];
            Rs[b * NPTS + j] = fmaf(p.y, rt, p.x * rb);
            rt = fmaf(p.x, rt, -(p.y * rb));
        }
        Rs[t * NPTS + j] = rt;
    }

    float* M = g_M + blockIdx.x * (NPTS * NPTS);
    for (int r = 0; r < NPTS; r++) M[r * NPTS + j] = Rs[r * NPTS + j];
}

__global__ void __launch_bounds__(256, 1)
matprod_kernel(int level, const float* __restrict__ mus) {
    __shared__ float As[NPTS * NPTS];
    __shared__ float Bs[NPTS * 32];

    const float* in  = (level == 0) ? g_M : (level == 1) ? g_P : g_Q;
    float*       out = (level == 0) ? g_P : (level == 1) ? g_Q : g_R;
    const int use_mus = (level == 2);

    const int p = blockIdx.x >> 1;
    const int h = blockIdx.x & 1;
    const float* A = in + (2 * p + 1) * (NPTS * NPTS);
    const float* B = in + (2 * p) * (NPTS * NPTS) + h * 32;
    float*       C = out + p * (NPTS * NPTS) + h * 32;

    for (int idx = threadIdx.x; idx < NPTS * NPTS; idx += 256) {
        const int k = idx >> 6, r = idx & 63;
        As[k * NPTS + r] = A[r * NPTS + k];
    }
    for (int idx = threadIdx.x; idx < NPTS * 32; idx += 256) {
        const int k = idx >> 5, jl = idx & 31;
        Bs[idx] = B[k * NPTS + jl];
    }
    __syncthreads();

    const int jl = threadIdx.x & 31;
    const int rq = threadIdx.x >> 5;

    float acc[8];
#pragma unroll
    for (int i = 0; i < 8; i++) acc[i] = 0.0f;

#pragma unroll 8
    for (int k = 0; k < NPTS; k++) {
        const float  b  = Bs[k * 32 + jl];
        const float4 a0 = *reinterpret_cast<const float4*>(&As[k * NPTS + rq * 8]);
        const float4 a1 = *reinterpret_cast<const float4*>(&As[k * NPTS + rq * 8 + 4]);
        acc[0] = fmaf(a0.x, b, acc[0]);
        acc[1] = fmaf(a0.y, b, acc[1]);
        acc[2] = fmaf(a0.z, b, acc[2]);
        acc[3] = fmaf(a0.w, b, acc[3]);
        acc[4] = fmaf(a1.x, b, acc[4]);
        acc[5] = fmaf(a1.y, b, acc[5]);
        acc[6] = fmaf(a1.z, b, acc[6]);
        acc[7] = fmaf(a1.w, b, acc[7]);
    }

#pragma unroll
    for (int i = 0; i < 8; i++) {
        const int r = rq * 8 + i;
        float v = acc[i];
        if (use_mus) v *= mus[r];
        C[r * NPTS + jl] = v;
    }
}

// ---------------------------------------------------------------------------
// GEMM: Y = R @ X, bf16 split 3-term HMMA, X staged through smem.
//  Stage: 8x LDG.128/thread -> cvt hi/lo once -> STS into [k][n] bf16 tiles
//         (pitch 68 u32; 68 mod 32 == 4 -> conflict-free ldmatrix rows).
//  B-frags: ldmatrix.x4.trans.b16 (canonical k-major-B pattern) — 2/warp/ks.
//  A-frags + epilogue: unchanged from the proven R5 kernel.
// Smem: RhiS 9216 | RloS 9216 | XhiS 17408 | XloS 17408 = 53248 B (occ 3).
// ---------------------------------------------------------------------------
#define LDR   36
#define LDX   68                      // u32 pitch of X bf16 tiles
#define RH_OFF 0
#define RL_OFF 9216
#define XH_OFF 18432
#define XL_OFF 35840
#define GEMM_SMEM 53248

#define CVT_PACK(d, x1, x0) \
    asm("cvt.rn.bf16x2.f32 %0, %1, %2;" : "=r"(d) : "f"(x1), "f"(x0))

#define LDMX4(R0, R1, R2, R3, ADDR)                                            \
    asm volatile("ldmatrix.sync.aligned.m8n8.x4.shared.b16 {%0,%1,%2,%3}, [%4];" \
                 : "=r"(R0), "=r"(R1), "=r"(R2), "=r"(R3) : "r"(ADDR))

#define LDMX4T(R0, R1, R2, R3, ADDR)                                           \
    asm volatile("ldmatrix.sync.aligned.m8n8.x4.trans.shared.b16 {%0,%1,%2,%3}, [%4];" \
                 : "=r"(R0), "=r"(R1), "=r"(R2), "=r"(R3) : "r"(ADDR))

#define MMA_BF16(ACC, A0, A1, A2, A3, B0, B1)                                  \
    asm volatile(                                                              \
        "mma.sync.aligned.m16n8k16.row.col.f32.bf16.bf16.f32 "                 \
        "{%0,%1,%2,%3},{%4,%5,%6,%7},{%8,%9},{%0,%1,%2,%3};"                   \
        : "+f"(ACC[0]), "+f"(ACC[1]), "+f"(ACC[2]), "+f"(ACC[3])               \
        : "r"(A0), "r"(A1), "r"(A2), "r"(A3), "r"(B0), "r"(B1))

extern __shared__ char smg[];

__global__ void __launch_bounds__(256, 3)
gemm_hmma_kernel(const float* __restrict__ X, float* __restrict__ Y) {
    u32* RhiS = reinterpret_cast<u32*>(smg + RH_OFF);
    u32* RloS = reinterpret_cast<u32*>(smg + RL_OFF);
    u32* XhiS = reinterpret_cast<u32*>(smg + XH_OFF);
    u32* XloS = reinterpret_cast<u32*>(smg + XL_OFF);

    const int tid = threadIdx.x;

    // ---- issue X tile loads first (64 rows x 128 cols, 8x LDG.128/thread) ----
    const float4* __restrict__ Xv = reinterpret_cast<const float4*>(X);
    const long nbase4 = (long)blockIdx.x * 32;
    float4 v[8];
#pragma unroll
    for (int q = 0; q < 8; q++) {
        const int i   = tid + 256 * q;
        const int row = i >> 5;
        const int c4  = i & 31;
        long col4 = nbase4 + c4;
        if (col4 > NCOLS / 4 - 1) col4 = NCOLS / 4 - 1;   // clamp (dup, unused)
        v[q] = Xv[(size_t)row * (NCOLS / 4) + col4];
    }

    // ---- pack R -> (hi, lo) while X loads are in flight ----
    for (int idx = tid; idx < NPTS * 32; idx += 256) {
        const int row = idx >> 5, kp = idx & 31;
        const float x0 = g_R[row * NPTS + 2 * kp];
        const float x1 = g_R[row * NPTS + 2 * kp + 1];
        u32 hh; CVT_PACK(hh, x1, x0);
        const float h0 = __uint_as_float(hh << 16);
        const float h1 = __uint_as_float(hh & 0xFFFF0000u);
        u32 ll; CVT_PACK(ll, x1 - h1, x0 - h0);
        RhiS[row * LDR + kp] = hh;
        RloS[row * LDR + kp] = ll;
    }

    // ---- convert X to bf16 hi/lo and store to [k][n] tiles ----
#pragma unroll
    for (int q = 0; q < 8; q++) {
        const int i   = tid + 256 * q;
        const int row = i >> 5;
        const int c4  = i & 31;
        const float4 f = v[q];
        u32 h01, h23;
        CVT_PACK(h01, f.y, f.x);
        CVT_PACK(h23, f.w, f.z);
        const float e0 = f.x - __uint_as_float(h01 << 16);
        const float e1 = f.y - __uint_as_float(h01 & 0xFFFF0000u);
        const float e2 = f.z - __uint_as_float(h23 << 16);
        const float e3 = f.w - __uint_as_float(h23 & 0xFFFF0000u);
        u32 l01, l23;
        CVT_PACK(l01, e1, e0);
        CVT_PACK(l23, e3, e2);
        u32* dh = XhiS + row * LDX + c4 * 2;
        u32* dl = XloS + row * LDX + c4 * 2;
        dh[0] = h01; dh[1] = h23;
        dl[0] = l01; dl[1] = l23;
    }
    __syncthreads();

    const int warp = tid >> 5;
    const int lane = tid & 31;
    const int g = lane >> 2;
    const int t = lane & 3;

    const long n0 = (long)blockIdx.x * 128 + warp * 16;
    if (n0 + 16 > NCOLS) return;   // after the sync: safe

    // A-frag ldmatrix base (proven layout)
    const int r8   = lane & 7;
    const int selm = (lane >> 3) & 1;
    const int selk = (lane >> 4) & 1;
    const u32 laneoffA = (u32)(((selm * 8 + r8) * LDR + selk * 4) * 4);
    const u32 ahibase  = smem_u32(RhiS) + laneoffA;
    const u32 alobase  = smem_u32(RloS) + laneoffA;

    // B-frag ldmatrix.trans base: tiles (k0,n0),(k8,n0),(k0,n8),(k8,n8)
    const int tileB = lane >> 3;      // 0..3
    const int rowB  = lane & 7;
    const u32 laneoffB =
        (u32)(((tileB & 1) * 8 + rowB) * (LDX * 4) + warp * 32 + (tileB >> 1) * 16);
    const u32 bhibase = smem_u32(XhiS) + laneoffB;
    const u32 blobase = smem_u32(XloS) + laneoffB;

    float acc[4][2][4];
#pragma unroll
    for (int mt = 0; mt < 4; mt++)
#pragma unroll
        for (int nt = 0; nt < 2; nt++)
#pragma unroll
            for (int q = 0; q < 4; q++) acc[mt][nt][q] = 0.0f;

#pragma unroll
    for (int ks = 0; ks < 4; ks++) {
        const u32 koff = (u32)(ks * 16 * LDX * 4);
        u32 bh0, bh1, bh2, bh3, bl0, bl1, bl2, bl3;
        LDMX4T(bh0, bh1, bh2, bh3, bhibase + koff);
        LDMX4T(bl0, bl1, bl2, bl3, blobase + koff);

#pragma unroll
        for (int mt = 0; mt < 4; mt++) {
            const u32 off = (u32)(mt * 16 * LDR * 4 + ks * 32);
            u32 ah0, ah1, ah2, ah3, al0, al1, al2, al3;
            LDMX4(ah0, ah1, ah2, ah3, ahibase + off);
            LDMX4(al0, al1, al2, al3, alobase + off);

            MMA_BF16(acc[mt][0], ah0, ah1, ah2, ah3, bh0, bh1);
            MMA_BF16(acc[mt][1], ah0, ah1, ah2, ah3, bh2, bh3);
            MMA_BF16(acc[mt][0], ah0, ah1, ah2, ah3, bl0, bl1);
            MMA_BF16(acc[mt][1], ah0, ah1, ah2, ah3, bl2, bl3);
            MMA_BF16(acc[mt][0], al0, al1, al2, al3, bh0, bh1);
            MMA_BF16(acc[mt][1], al0, al1, al2, al3, bh2, bh3);
        }
    }

#pragma unroll
    for (int mt = 0; mt < 4; mt++) {
        const int r0 = mt * 16 + g;
#pragma unroll
        for (int nt = 0; nt < 2; nt++) {
            const long col = n0 + 8 * nt + 2 * t;
            *reinterpret_cast<float2*>(Y + (size_t)r0 * NCOLS + col) =
                make_float2(acc[mt][nt][0], acc[mt][nt][1]);
            *reinterpret_cast<float2*>(Y + (size_t)(r0 + 8) * NCOLS + col) =
                make_float2(acc[mt][nt][2], acc[mt][nt][3]);
        }
    }
}

// ---------------------------------------------------------------------------
// Inputs (metadata order): X (64*300000 f32), angles (2016 f32), mus (64 f32).
// ---------------------------------------------------------------------------
extern "C" void kernel_launch(void* const* d_in, const int* in_sizes, int n_in,
                              void* d_out, int out_size) {
    const float* X      = (const float*)d_in[0];
    const float* angles = (const float*)d_in[1];
    const float* mus    = (const float*)d_in[2];
    float* Y            = (float*)d_out;

    static int configured = 0;
    if (!configured) {
        cudaFuncSetAttribute(gemm_hmma_kernel,
                             cudaFuncAttributeMaxDynamicSharedMemorySize, GEMM_SMEM);
        configured = 1;
    }

    build_seg_kernel<<<NSEG, NPTS>>>(angles);
    matprod_kernel<<<NSEG, 256>>>(0, mus);
    matprod_kernel<<<NSEG / 2, 256>>>(1, mus);
    matprod_kernel<<<NSEG / 4, 256>>>(2, mus);

    const int blocks = (NCOLS + 127) / 128;   // 2344
    gemm_hmma_kernel<<<blocks, 256, GEMM_SMEM>>>(X, Y);
}